// round 14
// baseline (speedup 1.0000x reference)
#include <cuda_runtime.h>
#include <math.h>

#define NN 100000
#define EE 1250000
#define H  64

typedef unsigned long long u64;

// ---------------- scratch (static __device__ — zero-initialized at load) ----------------
__device__ __align__(16) float g_bufA[NN * H];
__device__ __align__(16) float g_bufB[NN * H];
__device__ __align__(16) float g_t32 [NN * 32];
__device__ float g_dinv [NN];
__device__ float g_as   [NN];
__device__ float g_ad   [NN];
__device__ int   g_degi [NN];      // zeroed by k_scanB each run
__device__ int   g_scan [NN];
__device__ int   g_bsum [128];
__device__ int   g_row  [NN + 1];
__device__ int   g_cur  [NN];
__device__ int   g_csrc [EE];
__device__ int   g_asmax;          // reset to 0 by k_embed_final
__device__ __align__(16) float g_embed[H];   // zeroed by k_embed_final

__device__ __forceinline__ float leaky(float v) { return v > 0.f ? v : 0.2f * v; }
__device__ __forceinline__ int enc_f(float f) {
    int i = __float_as_int(f);
    return i >= 0 ? i : (i ^ 0x7FFFFFFF);
}
__device__ __forceinline__ float dec_f(int i) {
    return __int_as_float(i >= 0 ? i : (i ^ 0x7FFFFFFF));
}

// ---------------- f32x2 packed helpers ----------------
__device__ __forceinline__ u64 pack2(float lo, float hi) {
    u64 d; asm("mov.b64 %0, {%1, %2};" : "=l"(d) : "f"(lo), "f"(hi)); return d;
}
__device__ __forceinline__ void unpack2(u64 v, float& lo, float& hi) {
    asm("mov.b64 {%0, %1}, %2;" : "=f"(lo), "=f"(hi) : "l"(v));
}
__device__ __forceinline__ u64 fma2(u64 a, u64 b, u64 c) {
    u64 d; asm("fma.rn.f32x2 %0, %1, %2, %3;" : "=l"(d) : "l"(a), "l"(b), "l"(c)); return d;
}

// ---------------- degree histogram: 4 edges/thread ----------------
__global__ void k_deg(const int* __restrict__ dst, int e) {
    int base = (blockIdx.x * blockDim.x + threadIdx.x) * 4;
#pragma unroll
    for (int j = 0; j < 4; j++) {
        int i = base + j;
        if (i < e) atomicAdd(&g_degi[__ldg(&dst[i])], 1);
    }
}

// ---------------- scanA ----------------
__global__ void __launch_bounds__(1024) k_scanA(int n) {
    __shared__ int wsum[32];
    int i = blockIdx.x * 1024 + threadIdx.x;
    int lane = threadIdx.x & 31, wid = threadIdx.x >> 5;
    int v = (i < n) ? g_degi[i] : 0;
    int s = v;
#pragma unroll
    for (int o = 1; o < 32; o <<= 1) {
        int u = __shfl_up_sync(0xffffffffu, s, o);
        if (lane >= o) s += u;
    }
    if (lane == 31) wsum[wid] = s;
    __syncthreads();
    if (wid == 0) {
        int w = wsum[lane];
#pragma unroll
        for (int o = 1; o < 32; o <<= 1) {
            int u = __shfl_up_sync(0xffffffffu, w, o);
            if (lane >= o) w += u;
        }
        wsum[lane] = w;
    }
    __syncthreads();
    int off = wid ? wsum[wid - 1] : 0;
    s += off;
    if (i < n) g_scan[i] = s;
    if (threadIdx.x == 1023) g_bsum[blockIdx.x] = s;
}

// ---------------- scanB ----------------
__global__ void __launch_bounds__(1024) k_scanB(int n, int e) {
    __shared__ int s_off;
    int b = blockIdx.x;
    if (threadIdx.x < 32) {
        int lane = threadIdx.x;
        int acc = 0;
        for (int j = lane; j < b; j += 32) acc += g_bsum[j];
#pragma unroll
        for (int o = 16; o; o >>= 1) acc += __shfl_xor_sync(0xffffffffu, acc, o);
        if (lane == 0) s_off = acc;
    }
    __syncthreads();
    int i = b * 1024 + threadIdx.x;
    if (i < n) {
        int d = g_degi[i];
        int start = g_scan[i] - d + s_off;
        g_row[i] = start;
        g_cur[i] = start;
        g_dinv[i] = rsqrtf((float)(d + 1));
        g_degi[i] = 0;
    }
    if (i == 0) g_row[n] = e;
}

// ---------------- CSR scatter: 4 edges/thread ----------------
__global__ void k_csr(const int* __restrict__ src, const int* __restrict__ dst, int e) {
    int base = (blockIdx.x * blockDim.x + threadIdx.x) * 4;
#pragma unroll
    for (int j = 0; j < 4; j++) {
        int i = base + j;
        if (i < e) {
            int pos = atomicAdd(&g_cur[__ldg(&dst[i])], 1);
            g_csrc[pos] = __ldg(&src[i]);
        }
    }
}

// ---------------- gather in F=32 space (8 lanes/node), unroll 4 ----------------
__global__ void __launch_bounds__(256) k_gather32(const float* __restrict__ x,
                                                  float* __restrict__ t, int n)
{
    int tt = blockIdx.x * blockDim.x + threadIdx.x;
    int node = tt >> 3;
    if (node >= n) return;
    int c = tt & 7;

    int beg = g_row[node], end = g_row[node + 1];
    float dd = g_dinv[node];
    float4 self = __ldg((const float4*)x + (size_t)node * 8 + c);
    float4 acc = make_float4(self.x * dd, self.y * dd, self.z * dd, self.w * dd);

    int i = beg;
    for (; i + 4 <= end; i += 4) {
        int s0 = __ldg(&g_csrc[i]);
        int s1 = __ldg(&g_csrc[i + 1]);
        int s2 = __ldg(&g_csrc[i + 2]);
        int s3 = __ldg(&g_csrc[i + 3]);
        float d0 = __ldg(&g_dinv[s0]);
        float d1 = __ldg(&g_dinv[s1]);
        float d2 = __ldg(&g_dinv[s2]);
        float d3 = __ldg(&g_dinv[s3]);
        float4 v0 = __ldg((const float4*)x + (size_t)s0 * 8 + c);
        float4 v1 = __ldg((const float4*)x + (size_t)s1 * 8 + c);
        float4 v2 = __ldg((const float4*)x + (size_t)s2 * 8 + c);
        float4 v3 = __ldg((const float4*)x + (size_t)s3 * 8 + c);
        acc.x += (d0 * v0.x + d1 * v1.x) + (d2 * v2.x + d3 * v3.x);
        acc.y += (d0 * v0.y + d1 * v1.y) + (d2 * v2.y + d3 * v3.y);
        acc.z += (d0 * v0.z + d1 * v1.z) + (d2 * v2.z + d3 * v3.z);
        acc.w += (d0 * v0.w + d1 * v1.w) + (d2 * v2.w + d3 * v3.w);
    }
    for (; i < end; i++) {
        int s0 = __ldg(&g_csrc[i]);
        float d0 = __ldg(&g_dinv[s0]);
        float4 v0 = __ldg((const float4*)x + (size_t)s0 * 8 + c);
        acc.x += d0 * v0.x; acc.y += d0 * v0.y;
        acc.z += d0 * v0.z; acc.w += d0 * v0.w;
    }
    ((float4*)t)[(size_t)node * 8 + c] = acc;
}

// ---------------- gather in H=64 space (16 lanes/node), unroll 4 ----------------
__global__ void __launch_bounds__(256) k_gather64(const float* __restrict__ h,
                                                  float* __restrict__ u, int n)
{
    int tt = blockIdx.x * blockDim.x + threadIdx.x;
    int node = tt >> 4;
    if (node >= n) return;
    int c = tt & 15;

    int beg = g_row[node], end = g_row[node + 1];
    float dd = g_dinv[node];
    float4 self = __ldg((const float4*)h + (size_t)node * 16 + c);
    float4 acc = make_float4(self.x * dd, self.y * dd, self.z * dd, self.w * dd);

    int i = beg;
    for (; i + 4 <= end; i += 4) {
        int s0 = __ldg(&g_csrc[i]);
        int s1 = __ldg(&g_csrc[i + 1]);
        int s2 = __ldg(&g_csrc[i + 2]);
        int s3 = __ldg(&g_csrc[i + 3]);
        float d0 = __ldg(&g_dinv[s0]);
        float d1 = __ldg(&g_dinv[s1]);
        float d2 = __ldg(&g_dinv[s2]);
        float d3 = __ldg(&g_dinv[s3]);
        float4 v0 = __ldg((const float4*)h + (size_t)s0 * 16 + c);
        float4 v1 = __ldg((const float4*)h + (size_t)s1 * 16 + c);
        float4 v2 = __ldg((const float4*)h + (size_t)s2 * 16 + c);
        float4 v3 = __ldg((const float4*)h + (size_t)s3 * 16 + c);
        acc.x += (d0 * v0.x + d1 * v1.x) + (d2 * v2.x + d3 * v3.x);
        acc.y += (d0 * v0.y + d1 * v1.y) + (d2 * v2.y + d3 * v3.y);
        acc.z += (d0 * v0.z + d1 * v1.z) + (d2 * v2.z + d3 * v3.z);
        acc.w += (d0 * v0.w + d1 * v1.w) + (d2 * v2.w + d3 * v3.w);
    }
    for (; i < end; i++) {
        int s0 = __ldg(&g_csrc[i]);
        float d0 = __ldg(&g_dinv[s0]);
        float4 v0 = __ldg((const float4*)h + (size_t)s0 * 16 + c);
        acc.x += d0 * v0.x; acc.y += d0 * v0.y;
        acc.z += d0 * v0.z; acc.w += d0 * v0.w;
    }
    ((float4*)u)[(size_t)node * 16 + c] = acc;
}

// ---------------- GEMM (register-blocked, W-reuse): [n,K]@[K,64], 128 nodes/block ----
// Thread = 4 rows x 8 channels. Per k: 4 scalar x LDS + 2 LDS.128 of W (reused 4x).
// MODE 0: out = relu(dinv[node]*(in @ W) + bias)
// MODE 1: out = in @ W ; alpha dots ; global as-max
template <int K, int MODE>
__global__ void __launch_bounds__(256) k_gemm(
    const float* __restrict__ in, const float* __restrict__ W,
    float* __restrict__ out, const float* __restrict__ bias,
    const float* __restrict__ avs, const float* __restrict__ avd, int n)
{
    constexpr int PAD = ((K + 4) / 4) * 4;     // multiple of 4, K+ small pad
    __shared__ __align__(16) float Ws[K * H];
    __shared__ float xs[128 * PAD];
    __shared__ float as_s[H], ad_s[H], bs[H];
    __shared__ float smax[8];
    const int tid  = threadIdx.x;
    const int base = blockIdx.x * 128;

    for (int i = tid; i < K * H; i += 256) Ws[i] = W[i];
    if (MODE == 1 && tid < H) { as_s[tid] = avs[tid]; ad_s[tid] = avd[tid]; }
    if (MODE == 0 && tid < H) bs[tid] = bias[tid];

    int rows = n - base; if (rows > 128) rows = 128;
    for (int i = tid; i < rows * K; i += 256) {
        int r = i / K, c = i - r * K;
        xs[r * PAD + c] = in[(size_t)(base + r) * K + c];
    }
    if (rows < 128) {   // zero-fill tail rows so the mainloop is branch-free
        for (int i = rows * K + tid; i < 128 * K; i += 256) {
            int r = i / K, c = i - r * K;
            xs[r * PAD + c] = 0.f;
        }
    }
    __syncthreads();

    const int R0  = (tid >> 3) * 4;    // 4 rows per thread
    const int CH0 = (tid & 7) * 8;     // 8 channels per thread

    u64 a2[4][4];
#pragma unroll
    for (int j = 0; j < 4; j++)
#pragma unroll
        for (int q = 0; q < 4; q++) a2[j][q] = 0ull;

#pragma unroll 4
    for (int k = 0; k < K; k++) {
        ulonglong2 w0 = *(const ulonglong2*)&Ws[k * H + CH0];
        ulonglong2 w1 = *(const ulonglong2*)&Ws[k * H + CH0 + 4];
        float x0 = xs[(R0 + 0) * PAD + k];
        float x1 = xs[(R0 + 1) * PAD + k];
        float x2 = xs[(R0 + 2) * PAD + k];
        float x3 = xs[(R0 + 3) * PAD + k];
        u64 xp0 = pack2(x0, x0), xp1 = pack2(x1, x1);
        u64 xp2 = pack2(x2, x2), xp3 = pack2(x3, x3);
        a2[0][0] = fma2(xp0, w0.x, a2[0][0]); a2[0][1] = fma2(xp0, w0.y, a2[0][1]);
        a2[0][2] = fma2(xp0, w1.x, a2[0][2]); a2[0][3] = fma2(xp0, w1.y, a2[0][3]);
        a2[1][0] = fma2(xp1, w0.x, a2[1][0]); a2[1][1] = fma2(xp1, w0.y, a2[1][1]);
        a2[1][2] = fma2(xp1, w1.x, a2[1][2]); a2[1][3] = fma2(xp1, w1.y, a2[1][3]);
        a2[2][0] = fma2(xp2, w0.x, a2[2][0]); a2[2][1] = fma2(xp2, w0.y, a2[2][1]);
        a2[2][2] = fma2(xp2, w1.x, a2[2][2]); a2[2][3] = fma2(xp2, w1.y, a2[2][3]);
        a2[3][0] = fma2(xp3, w0.x, a2[3][0]); a2[3][1] = fma2(xp3, w0.y, a2[3][1]);
        a2[3][2] = fma2(xp3, w1.x, a2[3][2]); a2[3][3] = fma2(xp3, w1.y, a2[3][3]);
    }

    if (MODE == 0) {
#pragma unroll
        for (int j = 0; j < 4; j++) {
            int r = R0 + j;
            if (r >= rows) break;
            int node = base + r;
            float d = g_dinv[node];
            float a[8];
#pragma unroll
            for (int q = 0; q < 4; q++) unpack2(a2[j][q], a[2*q], a[2*q+1]);
            float4 o0, o1;
            o0.x = fmaxf(fmaf(a[0], d, bs[CH0+0]), 0.f);
            o0.y = fmaxf(fmaf(a[1], d, bs[CH0+1]), 0.f);
            o0.z = fmaxf(fmaf(a[2], d, bs[CH0+2]), 0.f);
            o0.w = fmaxf(fmaf(a[3], d, bs[CH0+3]), 0.f);
            o1.x = fmaxf(fmaf(a[4], d, bs[CH0+4]), 0.f);
            o1.y = fmaxf(fmaf(a[5], d, bs[CH0+5]), 0.f);
            o1.z = fmaxf(fmaf(a[6], d, bs[CH0+6]), 0.f);
            o1.w = fmaxf(fmaf(a[7], d, bs[CH0+7]), 0.f);
            float4* o4 = (float4*)&out[(size_t)node * H + CH0];
            o4[0] = o0; o4[1] = o1;
        }
    } else {
        float asr[4], adr[4];
#pragma unroll
        for (int j = 0; j < 4; j++) {
            float a[8];
#pragma unroll
            for (int q = 0; q < 4; q++) unpack2(a2[j][q], a[2*q], a[2*q+1]);
            float as = 0.f, ad = 0.f;
#pragma unroll
            for (int q = 0; q < 8; q++) {
                as = fmaf(a[q], as_s[CH0 + q], as);
                ad = fmaf(a[q], ad_s[CH0 + q], ad);
            }
            asr[j] = as; adr[j] = ad;
            int r = R0 + j;
            if (r < rows) {
                float4* o4 = (float4*)&out[(size_t)(base + r) * H + CH0];
                o4[0] = make_float4(a[0], a[1], a[2], a[3]);
                o4[1] = make_float4(a[4], a[5], a[6], a[7]);
            }
        }
        // reduce across the 8 ch-groups (lanes with same rg, xor 1/2/4)
#pragma unroll
        for (int o = 1; o < 8; o <<= 1) {
#pragma unroll
            for (int j = 0; j < 4; j++) {
                asr[j] += __shfl_xor_sync(0xffffffffu, asr[j], o);
                adr[j] += __shfl_xor_sync(0xffffffffu, adr[j], o);
            }
        }
        float amax = 0.f;
        if ((tid & 7) == 0) {
#pragma unroll
            for (int j = 0; j < 4; j++) {
                int r = R0 + j;
                if (r < rows) {
                    g_as[base + r] = asr[j];
                    g_ad[base + r] = adr[j];
                    amax = fmaxf(amax, asr[j]);
                }
            }
        }
#pragma unroll
        for (int o = 16; o; o >>= 1)
            amax = fmaxf(amax, __shfl_xor_sync(0xffffffffu, amax, o));
        if ((tid & 31) == 0) smax[tid >> 5] = amax;
        __syncthreads();
        if (tid == 0) {
            float m = smax[0];
#pragma unroll
            for (int w = 1; w < 8; w++) m = fmaxf(m, smax[w]);
            if (m > 0.f) atomicMax(&g_asmax, enc_f(m));
        }
    }
}

// ---------------- GAT gather: single pass, global-max shift, unroll 4 ----------------
__global__ void __launch_bounds__(256) k_gat_gather(
    const float* __restrict__ h2, const float* __restrict__ b2,
    float* __restrict__ out, int n)
{
    int t = blockIdx.x * blockDim.x + threadIdx.x;
    int node = t >> 4;
    if (node >= n) return;
    int c = t & 15;

    int beg = g_row[node], end = g_row[node + 1];
    float ad_d  = g_ad[node];
    float M     = dec_f(g_asmax);
    float m     = leaky(M + ad_d);
    float eself = leaky(g_as[node] + ad_d);

    float4 acc = make_float4(0.f, 0.f, 0.f, 0.f);
    float den = 0.f;
    int i = beg;
    for (; i + 4 <= end; i += 4) {
        int s0 = __ldg(&g_csrc[i]);
        int s1 = __ldg(&g_csrc[i + 1]);
        int s2 = __ldg(&g_csrc[i + 2]);
        int s3 = __ldg(&g_csrc[i + 3]);
        float a0 = __ldg(&g_as[s0]);
        float a1 = __ldg(&g_as[s1]);
        float a2 = __ldg(&g_as[s2]);
        float a3 = __ldg(&g_as[s3]);
        float4 v0 = __ldg((const float4*)h2 + (size_t)s0 * 16 + c);
        float4 v1 = __ldg((const float4*)h2 + (size_t)s1 * 16 + c);
        float4 v2 = __ldg((const float4*)h2 + (size_t)s2 * 16 + c);
        float4 v3 = __ldg((const float4*)h2 + (size_t)s3 * 16 + c);
        float p0 = __expf(leaky(a0 + ad_d) - m);
        float p1 = __expf(leaky(a1 + ad_d) - m);
        float p2 = __expf(leaky(a2 + ad_d) - m);
        float p3 = __expf(leaky(a3 + ad_d) - m);
        acc.x += (p0 * v0.x + p1 * v1.x) + (p2 * v2.x + p3 * v3.x);
        acc.y += (p0 * v0.y + p1 * v1.y) + (p2 * v2.y + p3 * v3.y);
        acc.z += (p0 * v0.z + p1 * v1.z) + (p2 * v2.z + p3 * v3.z);
        acc.w += (p0 * v0.w + p1 * v1.w) + (p2 * v2.w + p3 * v3.w);
        den += (p0 + p1) + (p2 + p3);
    }
    for (; i < end; i++) {
        int s0 = __ldg(&g_csrc[i]);
        float p0 = __expf(leaky(__ldg(&g_as[s0]) + ad_d) - m);
        float4 v0 = __ldg((const float4*)h2 + (size_t)s0 * 16 + c);
        acc.x += p0 * v0.x; acc.y += p0 * v0.y;
        acc.z += p0 * v0.z; acc.w += p0 * v0.w;
        den += p0;
    }

    float pself = __expf(eself - m);
    float w = 1.f / (den + pself);
    float4 hd = __ldg((const float4*)h2 + (size_t)node * 16 + c);
    float4 bb = __ldg((const float4*)b2 + c);
    float4 rr;
    rr.x = fmaxf(fmaf(acc.x + pself * hd.x, w, bb.x), 0.f);
    rr.y = fmaxf(fmaf(acc.y + pself * hd.y, w, bb.y), 0.f);
    rr.z = fmaxf(fmaf(acc.z + pself * hd.z, w, bb.z), 0.f);
    rr.w = fmaxf(fmaf(acc.w + pself * hd.w, w, bb.w), 0.f);
    ((float4*)&out[(size_t)node * H])[c] = rr;
}

// ---------------- GEMM3 + heads: register-blocked GEMM, h3 via smem, heads 2thr/node ----
__global__ void __launch_bounds__(256) k_gemm3_heads(
    const float* __restrict__ in, const float* __restrict__ W,
    const float* __restrict__ b3,
    const float* __restrict__ Wopt, const float* __restrict__ bopt,
    const float* __restrict__ Wb1,  const float* __restrict__ bb1,
    const float* __restrict__ Wb2,  const float* __restrict__ bb2,
    float* __restrict__ out_opt, float* __restrict__ out_bot, int n)
{
    constexpr int K = 64, PAD = 68;
    __shared__ __align__(16) float Ws[K * H];
    __shared__ __align__(16) float xs[128 * PAD];
    __shared__ float bs[H];
    __shared__ u64  sWopt2[32 * 10];     // packed channel pairs (2u, 2u+1)
    __shared__ u64  sWb12 [32 * 32];
    __shared__ float sbopt[10], sbb1[32], sWb2[32], sbb2[1];
    __shared__ float sEmb[H];
    const int tid  = threadIdx.x;
    const int base = blockIdx.x * 128;

    for (int i = tid; i < K * H; i += 256) Ws[i] = W[i];
    for (int i = tid; i < 320; i += 256) {
        int u = i / 10, c = i - u * 10;
        sWopt2[i] = pack2(Wopt[(2*u) * 10 + c], Wopt[(2*u+1) * 10 + c]);
    }
    for (int i = tid; i < 1024; i += 256) {
        int u = i >> 5, m = i & 31;
        sWb12[i] = pack2(Wb1[(2*u) * 32 + m], Wb1[(2*u+1) * 32 + m]);
    }
    if (tid < H)  { bs[tid] = b3[tid]; sEmb[tid] = 0.f; }
    if (tid < 32) { sbb1[tid] = bb1[tid]; sWb2[tid] = Wb2[tid]; }
    if (tid < 10) sbopt[tid] = bopt[tid];
    if (tid == 0) sbb2[0] = bb2[0];

    int rows = n - base; if (rows > 128) rows = 128;
    for (int i = tid; i < rows * K; i += 256) {
        int r = i / K, c = i - r * K;
        xs[r * PAD + c] = in[(size_t)(base + r) * K + c];
    }
    if (rows < 128) {
        for (int i = rows * K + tid; i < 128 * K; i += 256) {
            int r = i / K, c = i - r * K;
            xs[r * PAD + c] = 0.f;
        }
    }
    __syncthreads();

    const int R0  = (tid >> 3) * 4;
    const int CH0 = (tid & 7) * 8;

    u64 a2[4][4];
#pragma unroll
    for (int j = 0; j < 4; j++)
#pragma unroll
        for (int q = 0; q < 4; q++) a2[j][q] = 0ull;

#pragma unroll 4
    for (int k = 0; k < K; k++) {
        ulonglong2 w0 = *(const ulonglong2*)&Ws[k * H + CH0];
        ulonglong2 w1 = *(const ulonglong2*)&Ws[k * H + CH0 + 4];
        float x0 = xs[(R0 + 0) * PAD + k];
        float x1 = xs[(R0 + 1) * PAD + k];
        float x2 = xs[(R0 + 2) * PAD + k];
        float x3 = xs[(R0 + 3) * PAD + k];
        u64 xp0 = pack2(x0, x0), xp1 = pack2(x1, x1);
        u64 xp2 = pack2(x2, x2), xp3 = pack2(x3, x3);
        a2[0][0] = fma2(xp0, w0.x, a2[0][0]); a2[0][1] = fma2(xp0, w0.y, a2[0][1]);
        a2[0][2] = fma2(xp0, w1.x, a2[0][2]); a2[0][3] = fma2(xp0, w1.y, a2[0][3]);
        a2[1][0] = fma2(xp1, w0.x, a2[1][0]); a2[1][1] = fma2(xp1, w0.y, a2[1][1]);
        a2[1][2] = fma2(xp1, w1.x, a2[1][2]); a2[1][3] = fma2(xp1, w1.y, a2[1][3]);
        a2[2][0] = fma2(xp2, w0.x, a2[2][0]); a2[2][1] = fma2(xp2, w0.y, a2[2][1]);
        a2[2][2] = fma2(xp2, w1.x, a2[2][2]); a2[2][3] = fma2(xp2, w1.y, a2[2][3]);
        a2[3][0] = fma2(xp3, w0.x, a2[3][0]); a2[3][1] = fma2(xp3, w0.y, a2[3][1]);
        a2[3][2] = fma2(xp3, w1.x, a2[3][2]); a2[3][3] = fma2(xp3, w1.y, a2[3][3]);
    }
    __syncthreads();   // all reads of xs done; safe to overwrite with h3

    // h3 = relu(dinv*acc + b3); invalid rows get zeros (for embed correctness)
#pragma unroll
    for (int j = 0; j < 4; j++) {
        int r = R0 + j;
        bool valid = (r < rows);
        float d = valid ? g_dinv[base + r] : 0.f;
        float a[8];
#pragma unroll
        for (int q = 0; q < 4; q++) unpack2(a2[j][q], a[2*q], a[2*q+1]);
        float4 o0, o1;
        o0.x = valid ? fmaxf(fmaf(a[0], d, bs[CH0+0]), 0.f) : 0.f;
        o0.y = valid ? fmaxf(fmaf(a[1], d, bs[CH0+1]), 0.f) : 0.f;
        o0.z = valid ? fmaxf(fmaf(a[2], d, bs[CH0+2]), 0.f) : 0.f;
        o0.w = valid ? fmaxf(fmaf(a[3], d, bs[CH0+3]), 0.f) : 0.f;
        o1.x = valid ? fmaxf(fmaf(a[4], d, bs[CH0+4]), 0.f) : 0.f;
        o1.y = valid ? fmaxf(fmaf(a[5], d, bs[CH0+5]), 0.f) : 0.f;
        o1.z = valid ? fmaxf(fmaf(a[6], d, bs[CH0+6]), 0.f) : 0.f;
        o1.w = valid ? fmaxf(fmaf(a[7], d, bs[CH0+7]), 0.f) : 0.f;
        float4* p4 = (float4*)&xs[r * PAD + CH0];
        p4[0] = o0; p4[1] = o1;
    }
    __syncthreads();

    // ---- heads phase: 2 threads/node, half owns contiguous channels 32*half.. ----
    const int r     = tid >> 1;
    const bool valid = (r < rows);
    const int half  = tid & 1;
    const int node  = base + r;

    float acc[32];
    {
        const float4* p4 = (const float4*)&xs[r * PAD + half * 32];
#pragma unroll
        for (int q = 0; q < 8; q++) {
            float4 v = p4[q];
            acc[4*q] = v.x; acc[4*q+1] = v.y; acc[4*q+2] = v.z; acc[4*q+3] = v.w;
        }
    }
    u64 acc2[16];
#pragma unroll
    for (int j = 0; j < 16; j++) acc2[j] = pack2(acc[2*j], acc[2*j+1]);

    // opt logits: packed dots; pair index u = half*16 + i (contiguous halves)
#pragma unroll
    for (int c = 0; c < 10; c++) {
        u64 p2 = 0ull;
#pragma unroll
        for (int i = 0; i < 16; i++)
            p2 = fma2(acc2[i], sWopt2[(half * 16 + i) * 10 + c], p2);
        float plo, phi; unpack2(p2, plo, phi);
        float p = plo + phi;
        p += __shfl_xor_sync(0xffffffffu, p, 1);
        if (valid && half == 0) out_opt[(size_t)node * 10 + c] = p + sbopt[c];
    }

    // bottleneck MLP
    float z = 0.f;
#pragma unroll
    for (int m = 0; m < 32; m++) {
        u64 s2 = 0ull;
#pragma unroll
        for (int i = 0; i < 16; i++)
            s2 = fma2(acc2[i], sWb12[(half * 16 + i) * 32 + m], s2);
        float slo, shi; unpack2(s2, slo, shi);
        float s = slo + shi;
        s += __shfl_xor_sync(0xffffffffu, s, 1);
        z = fmaf(fmaxf(s + sbb1[m], 0.f), sWb2[m], z);
    }
    if (valid && half == 0) out_bot[node] = 1.f / (1.f + expf(-(z + sbb2[0])));

    // embedding: parity-preserving warp reduce, then smem, then global
    const int lane = tid & 31;
#pragma unroll
    for (int idx = 0; idx < 32; idx++) {
        float v = acc[idx];           // zeros for invalid rows (xs was zeroed)
        v += __shfl_xor_sync(0xffffffffu, v, 2);
        v += __shfl_xor_sync(0xffffffffu, v, 4);
        v += __shfl_xor_sync(0xffffffffu, v, 8);
        v += __shfl_xor_sync(0xffffffffu, v, 16);
        if (lane < 2) atomicAdd(&sEmb[half * 32 + idx], v);
    }
    __syncthreads();
    if (tid < H) atomicAdd(&g_embed[tid], sEmb[tid]);
}

__global__ void k_embed_final(float* __restrict__ emb_out, float inv_n) {
    int t = threadIdx.x;
    if (t < H) {
        emb_out[t] = g_embed[t] * inv_n;
        g_embed[t] = 0.f;
    }
    if (t == 0) g_asmax = 0;
}

// ---------------- launcher ----------------
extern "C" void kernel_launch(void* const* d_in, const int* in_sizes, int n_in,
                              void* d_out, int out_size)
{
    const float* x    = (const float*)d_in[0];
    const int*   ei   = (const int*)  d_in[1];
    const float* W1   = (const float*)d_in[2];
    const float* b1   = (const float*)d_in[3];
    const float* W2   = (const float*)d_in[4];
    const float* avs  = (const float*)d_in[5];
    const float* avd  = (const float*)d_in[6];
    const float* b2   = (const float*)d_in[7];
    const float* W3   = (const float*)d_in[8];
    const float* b3   = (const float*)d_in[9];
    const float* Wopt = (const float*)d_in[10];
    const float* bopt = (const float*)d_in[11];
    const float* Wb1  = (const float*)d_in[12];
    const float* bb1  = (const float*)d_in[13];
    const float* Wb2  = (const float*)d_in[14];
    const float* bb2  = (const float*)d_in[15];

    const int n = in_sizes[0] / 32;   // F = 32
    const int e = in_sizes[1] / 2;
    const int* src = ei;
    const int* dst = ei + e;

    float* out_opt = (float*)d_out;
    float* out_bot = out_opt + (size_t)n * 10;
    float* out_emb = out_bot + n;

    float *bufA = nullptr, *bufB = nullptr, *t32 = nullptr;
    cudaGetSymbolAddress((void**)&bufA, g_bufA);
    cudaGetSymbolAddress((void**)&bufB, g_bufB);
    cudaGetSymbolAddress((void**)&t32,  g_t32);

    const int B = 256;
    const int gE4  = (e + 1023) / 1024;
    const int gN8  = (n * 8  + B - 1) / B;
    const int gN16 = (n * 16 + B - 1) / B;
    const int gG   = (n + 127) / 128;
    const int nb   = (n + 1023) / 1024;

    // CSR build
    k_deg<<<gE4, B>>>(dst, e);
    k_scanA<<<nb, 1024>>>(n);
    k_scanB<<<nb, 1024>>>(n, e);
    k_csr<<<gE4, B>>>(src, dst, e);

    // GCN layer 1: aggregate in F=32 space, then transform
    k_gather32<<<gN8, B>>>(x, t32, n);
    k_gemm<32, 0><<<gG, 256>>>(t32, W1, bufB, b1, nullptr, nullptr, n);

    // GAT layer (single-pass softmax via global as-max)
    k_gemm<64, 1><<<gG, 256>>>(bufB, W2, bufA, nullptr, avs, avd, n);
    k_gat_gather<<<gN16, B>>>(bufA, b2, bufB, n);

    // GCN layer 3: aggregate-first, then fused transform + heads
    k_gather64<<<gN16, B>>>(bufB, bufA, n);
    k_gemm3_heads<<<gG, 256>>>(bufA, W3, b3, Wopt, bopt, Wb1, bb1, Wb2, bb2,
                               out_opt, out_bot, n);

    k_embed_final<<<1, 64>>>(out_emb, 1.0f / (float)n);
}

// round 15
// speedup vs baseline: 1.0441x; 1.0441x over previous
#include <cuda_runtime.h>
#include <math.h>

#define NN 100000
#define EE 1250000
#define H  64

typedef unsigned long long u64;

// ---------------- scratch (static __device__ — zero-initialized at load) ----------------
__device__ __align__(16) float g_bufA[NN * H];
__device__ __align__(16) float g_bufB[NN * H];
__device__ __align__(16) float g_t32 [NN * 32];
__device__ float g_dinv [NN];
__device__ float g_as   [NN];
__device__ float g_ad   [NN];
__device__ int   g_degi [NN];      // zeroed by k_scan each run
__device__ int   g_row  [NN + 1];
__device__ int   g_cur  [NN];
__device__ int   g_csrc [EE];
__device__ volatile int g_part[128];  // lookback state; re-zeroed by k_csr each run
__device__ int   g_asmax;          // reset to 0 by k_embed_final
__device__ __align__(16) float g_embed[H];   // zeroed by k_embed_final

__device__ __forceinline__ float leaky(float v) { return v > 0.f ? v : 0.2f * v; }
__device__ __forceinline__ int enc_f(float f) {
    int i = __float_as_int(f);
    return i >= 0 ? i : (i ^ 0x7FFFFFFF);
}
__device__ __forceinline__ float dec_f(int i) {
    return __int_as_float(i >= 0 ? i : (i ^ 0x7FFFFFFF));
}

// ---------------- f32x2 packed helpers ----------------
__device__ __forceinline__ u64 pack2(float lo, float hi) {
    u64 d; asm("mov.b64 %0, {%1, %2};" : "=l"(d) : "f"(lo), "f"(hi)); return d;
}
__device__ __forceinline__ void unpack2(u64 v, float& lo, float& hi) {
    asm("mov.b64 {%0, %1}, %2;" : "=f"(lo), "=f"(hi) : "l"(v));
}
__device__ __forceinline__ u64 fma2(u64 a, u64 b, u64 c) {
    u64 d; asm("fma.rn.f32x2 %0, %1, %2, %3;" : "=l"(d) : "l"(a), "l"(b), "l"(c)); return d;
}

// ---------------- degree histogram: 4 edges/thread ----------------
__global__ void k_deg(const int* __restrict__ dst, int e) {
    int base = (blockIdx.x * blockDim.x + threadIdx.x) * 4;
#pragma unroll
    for (int j = 0; j < 4; j++) {
        int i = base + j;
        if (i < e) atomicAdd(&g_degi[__ldg(&dst[i])], 1);
    }
}

// ---------------- single-pass scan (decoupled lookback) + finalize row/cur/dinv ----------
// 98 blocks, all resident (<=148 SMs) -> lookback spin is deadlock-free.
// g_part slots: 0 = invalid, (1<<30)|aggregate, (2<<30)|inclusive-prefix. Sums < 2^21.
__global__ void __launch_bounds__(1024) k_scan(int n, int e) {
    __shared__ int wsum[32];
    __shared__ int s_off;
    const int b = blockIdx.x;
    const int i = b * 1024 + threadIdx.x;
    const int lane = threadIdx.x & 31, wid = threadIdx.x >> 5;

    int v = (i < n) ? g_degi[i] : 0;
    int s = v;
#pragma unroll
    for (int o = 1; o < 32; o <<= 1) {
        int u = __shfl_up_sync(0xffffffffu, s, o);
        if (lane >= o) s += u;
    }
    if (lane == 31) wsum[wid] = s;
    __syncthreads();
    if (wid == 0) {
        int w = wsum[lane];
#pragma unroll
        for (int o = 1; o < 32; o <<= 1) {
            int u = __shfl_up_sync(0xffffffffu, w, o);
            if (lane >= o) w += u;
        }
        wsum[lane] = w;
    }
    __syncthreads();
    int off = wid ? wsum[wid - 1] : 0;
    s += off;                          // inclusive within block
    const int total = wsum[31];        // block total

    if (threadIdx.x == 0) {
        if (b == 0) {
            g_part[0] = (2 << 30) | total;
            s_off = 0;
        } else {
            g_part[b] = (1 << 30) | total;
            int sum = 0;
            int j = b - 1;
            while (true) {
                int p = g_part[j];
                int st = (unsigned)p >> 30;
                if (st == 0) continue;          // spin: predecessor not published yet
                sum += p & 0x3FFFFFFF;
                if (st == 2) break;             // hit an inclusive prefix
                j--;
            }
            g_part[b] = (2 << 30) | (sum + total);
            s_off = sum;
        }
    }
    __syncthreads();
    const int off2 = s_off;
    if (i < n) {
        int start = s - v + off2;      // exclusive prefix for node i
        g_row[i] = start;
        g_cur[i] = start;
        g_dinv[i] = rsqrtf((float)(v + 1));   // +1 self-loop
        g_degi[i] = 0;                 // restore zero for next run
    }
    if (i == 0) g_row[n] = e;
}

// ---------------- CSR scatter: 4 edges/thread; also restores g_part to zero -------------
__global__ void k_csr(const int* __restrict__ src, const int* __restrict__ dst, int e) {
    int t = blockIdx.x * blockDim.x + threadIdx.x;
    if (t < 128) g_part[t] = 0;        // reset lookback state for next run
    int base = t * 4;
#pragma unroll
    for (int j = 0; j < 4; j++) {
        int i = base + j;
        if (i < e) {
            int sv = __ldg(&src[i]);   // hoist independent load ahead of the atomic
            int pos = atomicAdd(&g_cur[__ldg(&dst[i])], 1);
            g_csrc[pos] = sv;
        }
    }
}

// ---------------- gather in F=32 space (8 lanes/node), unroll 4 ----------------
__global__ void __launch_bounds__(256) k_gather32(const float* __restrict__ x,
                                                  float* __restrict__ t, int n)
{
    int tt = blockIdx.x * blockDim.x + threadIdx.x;
    int node = tt >> 3;
    if (node >= n) return;
    int c = tt & 7;

    int beg = g_row[node], end = g_row[node + 1];
    float dd = g_dinv[node];
    float4 self = __ldg((const float4*)x + (size_t)node * 8 + c);
    float4 acc = make_float4(self.x * dd, self.y * dd, self.z * dd, self.w * dd);

    int i = beg;
    for (; i + 4 <= end; i += 4) {
        int s0 = __ldg(&g_csrc[i]);
        int s1 = __ldg(&g_csrc[i + 1]);
        int s2 = __ldg(&g_csrc[i + 2]);
        int s3 = __ldg(&g_csrc[i + 3]);
        float d0 = __ldg(&g_dinv[s0]);
        float d1 = __ldg(&g_dinv[s1]);
        float d2 = __ldg(&g_dinv[s2]);
        float d3 = __ldg(&g_dinv[s3]);
        float4 v0 = __ldg((const float4*)x + (size_t)s0 * 8 + c);
        float4 v1 = __ldg((const float4*)x + (size_t)s1 * 8 + c);
        float4 v2 = __ldg((const float4*)x + (size_t)s2 * 8 + c);
        float4 v3 = __ldg((const float4*)x + (size_t)s3 * 8 + c);
        acc.x += (d0 * v0.x + d1 * v1.x) + (d2 * v2.x + d3 * v3.x);
        acc.y += (d0 * v0.y + d1 * v1.y) + (d2 * v2.y + d3 * v3.y);
        acc.z += (d0 * v0.z + d1 * v1.z) + (d2 * v2.z + d3 * v3.z);
        acc.w += (d0 * v0.w + d1 * v1.w) + (d2 * v2.w + d3 * v3.w);
    }
    for (; i < end; i++) {
        int s0 = __ldg(&g_csrc[i]);
        float d0 = __ldg(&g_dinv[s0]);
        float4 v0 = __ldg((const float4*)x + (size_t)s0 * 8 + c);
        acc.x += d0 * v0.x; acc.y += d0 * v0.y;
        acc.z += d0 * v0.z; acc.w += d0 * v0.w;
    }
    ((float4*)t)[(size_t)node * 8 + c] = acc;
}

// ---------------- gather in H=64 space (16 lanes/node), unroll 4 ----------------
__global__ void __launch_bounds__(256) k_gather64(const float* __restrict__ h,
                                                  float* __restrict__ u, int n)
{
    int tt = blockIdx.x * blockDim.x + threadIdx.x;
    int node = tt >> 4;
    if (node >= n) return;
    int c = tt & 15;

    int beg = g_row[node], end = g_row[node + 1];
    float dd = g_dinv[node];
    float4 self = __ldg((const float4*)h + (size_t)node * 16 + c);
    float4 acc = make_float4(self.x * dd, self.y * dd, self.z * dd, self.w * dd);

    int i = beg;
    for (; i + 4 <= end; i += 4) {
        int s0 = __ldg(&g_csrc[i]);
        int s1 = __ldg(&g_csrc[i + 1]);
        int s2 = __ldg(&g_csrc[i + 2]);
        int s3 = __ldg(&g_csrc[i + 3]);
        float d0 = __ldg(&g_dinv[s0]);
        float d1 = __ldg(&g_dinv[s1]);
        float d2 = __ldg(&g_dinv[s2]);
        float d3 = __ldg(&g_dinv[s3]);
        float4 v0 = __ldg((const float4*)h + (size_t)s0 * 16 + c);
        float4 v1 = __ldg((const float4*)h + (size_t)s1 * 16 + c);
        float4 v2 = __ldg((const float4*)h + (size_t)s2 * 16 + c);
        float4 v3 = __ldg((const float4*)h + (size_t)s3 * 16 + c);
        acc.x += (d0 * v0.x + d1 * v1.x) + (d2 * v2.x + d3 * v3.x);
        acc.y += (d0 * v0.y + d1 * v1.y) + (d2 * v2.y + d3 * v3.y);
        acc.z += (d0 * v0.z + d1 * v1.z) + (d2 * v2.z + d3 * v3.z);
        acc.w += (d0 * v0.w + d1 * v1.w) + (d2 * v2.w + d3 * v3.w);
    }
    for (; i < end; i++) {
        int s0 = __ldg(&g_csrc[i]);
        float d0 = __ldg(&g_dinv[s0]);
        float4 v0 = __ldg((const float4*)h + (size_t)s0 * 16 + c);
        acc.x += d0 * v0.x; acc.y += d0 * v0.y;
        acc.z += d0 * v0.z; acc.w += d0 * v0.w;
    }
    ((float4*)u)[(size_t)node * 16 + c] = acc;
}

// ---------------- GEMM (f32x2, R12-proven layout): [n,K]@[K,64], 128 nodes/block ----
// MODE 0: out = relu(dinv[node]*(in @ W) + bias)
// MODE 1: out = in @ W ; alpha dots ; global as-max
template <int K, int MODE>
__global__ void __launch_bounds__(256) k_gemm(
    const float* __restrict__ in, const float* __restrict__ W,
    float* __restrict__ out, const float* __restrict__ bias,
    const float* __restrict__ avs, const float* __restrict__ avd, int n)
{
    constexpr int PAD = K + 1;                 // odd -> conflict-free
    __shared__ __align__(16) float Ws[K * H];
    __shared__ float xs[128 * PAD];
    __shared__ float as_s[H], ad_s[H], bs[H];
    __shared__ float smax[8];
    const int tid  = threadIdx.x;
    const int base = blockIdx.x * 128;

    for (int i = tid; i < K * H; i += 256) Ws[i] = W[i];
    if (MODE == 1 && tid < H) { as_s[tid] = avs[tid]; ad_s[tid] = avd[tid]; }
    if (MODE == 0 && tid < H) bs[tid] = bias[tid];

    int rows = n - base; if (rows > 128) rows = 128;
    for (int i = tid; i < rows * K; i += 256) {
        int r = i / K, c = i - r * K;
        xs[r * PAD + c] = in[(size_t)(base + r) * K + c];
    }
    __syncthreads();

    const int r     = tid >> 1;
    const bool valid = (r < rows);
    const int rc    = valid ? r : 0;
    const int half  = tid & 1;

    u64 acc2[16];
#pragma unroll
    for (int j = 0; j < 16; j++) acc2[j] = 0ull;

    const float* xrow = &xs[rc * PAD];
    const ulonglong2* w2 = (const ulonglong2*)Ws;
#pragma unroll 4
    for (int k = 0; k < K; k++) {
        float xv = xrow[k];
        u64 xv2 = pack2(xv, xv);
        const ulonglong2* wk = w2 + k * 16 + half;
#pragma unroll
        for (int j = 0; j < 8; j++) {
            ulonglong2 wv = wk[j * 2];
            acc2[2*j]   = fma2(xv2, wv.x, acc2[2*j]);
            acc2[2*j+1] = fma2(xv2, wv.y, acc2[2*j+1]);
        }
    }

    float acc[32];
#pragma unroll
    for (int j = 0; j < 16; j++) unpack2(acc2[j], acc[2*j], acc[2*j+1]);

    const int node = base + r;
    if (MODE == 0) {
        if (!valid) return;
        float d = g_dinv[node];
        float4* o4 = (float4*)&out[(size_t)node * H];
#pragma unroll
        for (int j = 0; j < 8; j++) {
            int ch = (j * 2 + half) * 4;
            o4[j * 2 + half] = make_float4(
                fmaxf(fmaf(acc[4*j+0], d, bs[ch+0]), 0.f),
                fmaxf(fmaf(acc[4*j+1], d, bs[ch+1]), 0.f),
                fmaxf(fmaf(acc[4*j+2], d, bs[ch+2]), 0.f),
                fmaxf(fmaf(acc[4*j+3], d, bs[ch+3]), 0.f));
        }
    } else {
        float as = 0.f, ad = 0.f;
#pragma unroll
        for (int j = 0; j < 8; j++) {
#pragma unroll
            for (int q = 0; q < 4; q++) {
                int ch = (j * 2 + half) * 4 + q;
                as = fmaf(acc[4*j+q], as_s[ch], as);
                ad = fmaf(acc[4*j+q], ad_s[ch], ad);
            }
        }
        as += __shfl_xor_sync(0xffffffffu, as, 1);
        ad += __shfl_xor_sync(0xffffffffu, ad, 1);
        if (valid) {
            if (half == 0) { g_as[node] = as; g_ad[node] = ad; }
            float4* o4 = (float4*)&out[(size_t)node * H];
#pragma unroll
            for (int j = 0; j < 8; j++)
                o4[j * 2 + half] = make_float4(acc[4*j], acc[4*j+1], acc[4*j+2], acc[4*j+3]);
        }
        float amax = valid ? as : 0.f;
#pragma unroll
        for (int o = 16; o; o >>= 1)
            amax = fmaxf(amax, __shfl_xor_sync(0xffffffffu, amax, o));
        if ((tid & 31) == 0) smax[tid >> 5] = amax;
        __syncthreads();
        if (tid == 0) {
            float m = smax[0];
#pragma unroll
            for (int w = 1; w < 8; w++) m = fmaxf(m, smax[w]);
            if (m > 0.f) atomicMax(&g_asmax, enc_f(m));
        }
    }
}

// ---------------- GAT gather: single pass, global-max shift, unroll 4 ----------------
__global__ void __launch_bounds__(256) k_gat_gather(
    const float* __restrict__ h2, const float* __restrict__ b2,
    float* __restrict__ out, int n)
{
    int t = blockIdx.x * blockDim.x + threadIdx.x;
    int node = t >> 4;
    if (node >= n) return;
    int c = t & 15;

    int beg = g_row[node], end = g_row[node + 1];
    float ad_d  = g_ad[node];
    float M     = dec_f(g_asmax);
    float m     = leaky(M + ad_d);
    float eself = leaky(g_as[node] + ad_d);

    float4 acc = make_float4(0.f, 0.f, 0.f, 0.f);
    float den = 0.f;
    int i = beg;
    for (; i + 4 <= end; i += 4) {
        int s0 = __ldg(&g_csrc[i]);
        int s1 = __ldg(&g_csrc[i + 1]);
        int s2 = __ldg(&g_csrc[i + 2]);
        int s3 = __ldg(&g_csrc[i + 3]);
        float a0 = __ldg(&g_as[s0]);
        float a1 = __ldg(&g_as[s1]);
        float a2 = __ldg(&g_as[s2]);
        float a3 = __ldg(&g_as[s3]);
        float4 v0 = __ldg((const float4*)h2 + (size_t)s0 * 16 + c);
        float4 v1 = __ldg((const float4*)h2 + (size_t)s1 * 16 + c);
        float4 v2 = __ldg((const float4*)h2 + (size_t)s2 * 16 + c);
        float4 v3 = __ldg((const float4*)h2 + (size_t)s3 * 16 + c);
        float p0 = __expf(leaky(a0 + ad_d) - m);
        float p1 = __expf(leaky(a1 + ad_d) - m);
        float p2 = __expf(leaky(a2 + ad_d) - m);
        float p3 = __expf(leaky(a3 + ad_d) - m);
        acc.x += (p0 * v0.x + p1 * v1.x) + (p2 * v2.x + p3 * v3.x);
        acc.y += (p0 * v0.y + p1 * v1.y) + (p2 * v2.y + p3 * v3.y);
        acc.z += (p0 * v0.z + p1 * v1.z) + (p2 * v2.z + p3 * v3.z);
        acc.w += (p0 * v0.w + p1 * v1.w) + (p2 * v2.w + p3 * v3.w);
        den += (p0 + p1) + (p2 + p3);
    }
    for (; i < end; i++) {
        int s0 = __ldg(&g_csrc[i]);
        float p0 = __expf(leaky(__ldg(&g_as[s0]) + ad_d) - m);
        float4 v0 = __ldg((const float4*)h2 + (size_t)s0 * 16 + c);
        acc.x += p0 * v0.x; acc.y += p0 * v0.y;
        acc.z += p0 * v0.z; acc.w += p0 * v0.w;
        den += p0;
    }

    float pself = __expf(eself - m);
    float w = 1.f / (den + pself);
    float4 hd = __ldg((const float4*)h2 + (size_t)node * 16 + c);
    float4 bb = __ldg((const float4*)b2 + c);
    float4 rr;
    rr.x = fmaxf(fmaf(acc.x + pself * hd.x, w, bb.x), 0.f);
    rr.y = fmaxf(fmaf(acc.y + pself * hd.y, w, bb.y), 0.f);
    rr.z = fmaxf(fmaf(acc.z + pself * hd.z, w, bb.z), 0.f);
    rr.w = fmaxf(fmaf(acc.w + pself * hd.w, w, bb.w), 0.f);
    ((float4*)&out[(size_t)node * H])[c] = rr;
}

// ---------------- GEMM3 + heads (f32x2 mainloop + packed head dots, R12 layout) -------
__global__ void __launch_bounds__(256) k_gemm3_heads(
    const float* __restrict__ in, const float* __restrict__ W,
    const float* __restrict__ b3,
    const float* __restrict__ Wopt, const float* __restrict__ bopt,
    const float* __restrict__ Wb1,  const float* __restrict__ bb1,
    const float* __restrict__ Wb2,  const float* __restrict__ bb2,
    float* __restrict__ out_opt, float* __restrict__ out_bot, int n)
{
    constexpr int K = 64, PAD = K + 1;
    __shared__ __align__(16) float Ws[K * H];
    __shared__ float xs[128 * PAD];
    __shared__ float bs[H];
    __shared__ u64  sWopt2[32 * 10];     // packed (2u, 2u+1) channel pairs
    __shared__ u64  sWb12 [32 * 32];
    __shared__ float sbopt[10], sbb1[32], sWb2[32], sbb2[1];
    __shared__ float sEmb[H];
    const int tid  = threadIdx.x;
    const int base = blockIdx.x * 128;

    for (int i = tid; i < K * H; i += 256) Ws[i] = W[i];
    for (int i = tid; i < 320; i += 256) {
        int u = i / 10, c = i - u * 10;
        sWopt2[i] = pack2(Wopt[(2*u) * 10 + c], Wopt[(2*u+1) * 10 + c]);
    }
    for (int i = tid; i < 1024; i += 256) {
        int u = i >> 5, m = i & 31;
        sWb12[i] = pack2(Wb1[(2*u) * 32 + m], Wb1[(2*u+1) * 32 + m]);
    }
    if (tid < H)  { bs[tid] = b3[tid]; sEmb[tid] = 0.f; }
    if (tid < 32) { sbb1[tid] = bb1[tid]; sWb2[tid] = Wb2[tid]; }
    if (tid < 10) sbopt[tid] = bopt[tid];
    if (tid == 0) sbb2[0] = bb2[0];

    int rows = n - base; if (rows > 128) rows = 128;
    for (int i = tid; i < rows * K; i += 256) {
        int r = i / K, c = i - r * K;
        xs[r * PAD + c] = in[(size_t)(base + r) * K + c];
    }
    __syncthreads();

    const int r     = tid >> 1;
    const bool valid = (r < rows);
    const int rc    = valid ? r : 0;
    const int half  = tid & 1;

    u64 acc2[16];
#pragma unroll
    for (int j = 0; j < 16; j++) acc2[j] = 0ull;

    const float* xrow = &xs[rc * PAD];
    const ulonglong2* w2 = (const ulonglong2*)Ws;
#pragma unroll 4
    for (int k = 0; k < K; k++) {
        float xv = xrow[k];
        u64 xv2 = pack2(xv, xv);
        const ulonglong2* wk = w2 + k * 16 + half;
#pragma unroll
        for (int j = 0; j < 8; j++) {
            ulonglong2 wv = wk[j * 2];
            acc2[2*j]   = fma2(xv2, wv.x, acc2[2*j]);
            acc2[2*j+1] = fma2(xv2, wv.y, acc2[2*j+1]);
        }
    }

    const int node = base + r;
    float d = valid ? g_dinv[node] : 0.f;

    // h3 = relu(d*acc + b3[ch]); zero for invalid threads; then repack
    float acc[32];
#pragma unroll
    for (int j = 0; j < 16; j++) unpack2(acc2[j], acc[2*j], acc[2*j+1]);
#pragma unroll
    for (int j = 0; j < 8; j++) {
#pragma unroll
        for (int q = 0; q < 4; q++) {
            int ch = (j * 2 + half) * 4 + q;
            float v = fmaxf(fmaf(acc[4*j+q], d, bs[ch]), 0.f);
            acc[4*j+q] = valid ? v : 0.f;
        }
    }
#pragma unroll
    for (int j = 0; j < 16; j++) acc2[j] = pack2(acc[2*j], acc[2*j+1]);

    // opt logits: packed dots; pair index u = (i>>1)*4 + half*2 + (i&1)
#pragma unroll
    for (int c = 0; c < 10; c++) {
        u64 p2 = 0ull;
#pragma unroll
        for (int i = 0; i < 16; i++) {
            int u = (i >> 1) * 4 + half * 2 + (i & 1);
            p2 = fma2(acc2[i], sWopt2[u * 10 + c], p2);
        }
        float plo, phi; unpack2(p2, plo, phi);
        float p = plo + phi;
        p += __shfl_xor_sync(0xffffffffu, p, 1);
        if (valid && half == 0) out_opt[(size_t)node * 10 + c] = p + sbopt[c];
    }

    // bottleneck MLP: packed dots
    float z = 0.f;
#pragma unroll
    for (int m = 0; m < 32; m++) {
        u64 s2 = 0ull;
#pragma unroll
        for (int i = 0; i < 16; i++) {
            int u = (i >> 1) * 4 + half * 2 + (i & 1);
            s2 = fma2(acc2[i], sWb12[u * 32 + m], s2);
        }
        float slo, shi; unpack2(s2, slo, shi);
        float s = slo + shi;
        s += __shfl_xor_sync(0xffffffffu, s, 1);
        z = fmaf(fmaxf(s + sbb1[m], 0.f), sWb2[m], z);
    }
    if (valid && half == 0) out_bot[node] = 1.f / (1.f + expf(-(z + sbb2[0])));

    // embedding: parity-preserving warp reduce, then smem, then global
    const int lane = tid & 31;
#pragma unroll
    for (int idx = 0; idx < 32; idx++) {
        float v = acc[idx];
        v += __shfl_xor_sync(0xffffffffu, v, 2);
        v += __shfl_xor_sync(0xffffffffu, v, 4);
        v += __shfl_xor_sync(0xffffffffu, v, 8);
        v += __shfl_xor_sync(0xffffffffu, v, 16);
        if (lane < 2) {
            int ch = ((idx >> 2) * 2 + half) * 4 + (idx & 3);
            atomicAdd(&sEmb[ch], v);
        }
    }
    __syncthreads();
    if (tid < H) atomicAdd(&g_embed[tid], sEmb[tid]);
}

__global__ void k_embed_final(float* __restrict__ emb_out, float inv_n) {
    int t = threadIdx.x;
    if (t < H) {
        emb_out[t] = g_embed[t] * inv_n;
        g_embed[t] = 0.f;
    }
    if (t == 0) g_asmax = 0;
}

// ---------------- launcher ----------------
extern "C" void kernel_launch(void* const* d_in, const int* in_sizes, int n_in,
                              void* d_out, int out_size)
{
    const float* x    = (const float*)d_in[0];
    const int*   ei   = (const int*)  d_in[1];
    const float* W1   = (const float*)d_in[2];
    const float* b1   = (const float*)d_in[3];
    const float* W2   = (const float*)d_in[4];
    const float* avs  = (const float*)d_in[5];
    const float* avd  = (const float*)d_in[6];
    const float* b2   = (const float*)d_in[7];
    const float* W3   = (const float*)d_in[8];
    const float* b3   = (const float*)d_in[9];
    const float* Wopt = (const float*)d_in[10];
    const float* bopt = (const float*)d_in[11];
    const float* Wb1  = (const float*)d_in[12];
    const float* bb1  = (const float*)d_in[13];
    const float* Wb2  = (const float*)d_in[14];
    const float* bb2  = (const float*)d_in[15];

    const int n = in_sizes[0] / 32;   // F = 32
    const int e = in_sizes[1] / 2;
    const int* src = ei;
    const int* dst = ei + e;

    float* out_opt = (float*)d_out;
    float* out_bot = out_opt + (size_t)n * 10;
    float* out_emb = out_bot + n;

    float *bufA = nullptr, *bufB = nullptr, *t32 = nullptr;
    cudaGetSymbolAddress((void**)&bufA, g_bufA);
    cudaGetSymbolAddress((void**)&bufB, g_bufB);
    cudaGetSymbolAddress((void**)&t32,  g_t32);

    const int B = 256;
    const int gE4  = (e + 1023) / 1024;         // 4 edges/thread
    const int gN8  = (n * 8  + B - 1) / B;
    const int gN16 = (n * 16 + B - 1) / B;
    const int gG   = (n + 127) / 128;
    const int nb   = (n + 1023) / 1024;

    // CSR build: degree histogram -> single-pass lookback scan -> cursor scatter
    k_deg<<<gE4, B>>>(dst, e);
    k_scan<<<nb, 1024>>>(n, e);
    k_csr<<<gE4, B>>>(src, dst, e);

    // GCN layer 1: aggregate in F=32 space, then transform
    k_gather32<<<gN8, B>>>(x, t32, n);
    k_gemm<32, 0><<<gG, 256>>>(t32, W1, bufB, b1, nullptr, nullptr, n);

    // GAT layer (single-pass softmax via global as-max)
    k_gemm<64, 1><<<gG, 256>>>(bufB, W2, bufA, nullptr, avs, avd, n);
    k_gat_gather<<<gN16, B>>>(bufA, b2, bufB, n);

    // GCN layer 3: aggregate-first, then fused transform + heads
    k_gather64<<<gN16, B>>>(bufB, bufA, n);
    k_gemm3_heads<<<gG, 256>>>(bufA, W3, b3, Wopt, bopt, Wb1, bb1, Wb2, bb2,
                               out_opt, out_bot, n);

    k_embed_final<<<1, 64>>>(out_emb, 1.0f / (float)n);
}